// round 16
// baseline (speedup 1.0000x reference)
#include <cuda_runtime.h>
#include <cuda_fp16.h>
#include <math.h>
#include <stdint.h>

#define BQ 4
#define LQ 4096
#define DQ 1024
#define HQ 2048
#define BLQ 16384
#define NCH 32            // scan chunks
#define CLEN 128          // steps per chunk (NCH*CLEN = LQ)

// Scratch
__device__ __half  g_xnh[(size_t)BLQ * DQ];
__device__ __half  g_hh [(size_t)BLQ * HQ];          // h, then ff
__device__ __half  g_wh [6 * (size_t)HQ * DQ];       // wpfi(2), wpfcfa(2), whho(1), whfo(1)
__device__ __half2 g_rz [(size_t)BLQ * HQ];
__device__ float g_x1[(size_t)BLQ * DQ];
__device__ float g_sA[NCH * 8192];
__device__ float g_sB[NCH * 8192];
__device__ float g_sS[NCH * 8192];

__device__ __forceinline__ void cp_async16(uint32_t saddr, const void* gptr) {
    asm volatile("cp.async.cg.shared.global [%0], [%1], 16;" :: "r"(saddr), "l"(gptr));
}
__device__ __forceinline__ void cp_commit() {
    asm volatile("cp.async.commit_group;" ::: "memory");
}
template <int N>
__device__ __forceinline__ void cp_wait() {
    asm volatile("cp.async.wait_group %0;" :: "n"(N) : "memory");
}
__device__ __forceinline__ uint32_t smem_u32(const void* p) {
    uint32_t a;
    asm("{ .reg .u64 t; cvta.to.shared.u64 t, %1; cvt.u32.u64 %0, t; }"
        : "=r"(a) : "l"(p));
    return a;
}
__device__ __forceinline__ void ldsm_x4(uint32_t* r, uint32_t addr) {
    asm volatile("ldmatrix.sync.aligned.m8n8.x4.shared.b16 {%0,%1,%2,%3}, [%4];"
        : "=r"(r[0]), "=r"(r[1]), "=r"(r[2]), "=r"(r[3]) : "r"(addr));
}
__device__ __forceinline__ void mma_f16(float* c, const uint32_t* a, const uint32_t* b) {
    asm volatile(
        "mma.sync.aligned.m16n8k16.row.col.f32.f16.f16.f32 "
        "{%0,%1,%2,%3}, {%4,%5,%6,%7}, {%8,%9}, {%0,%1,%2,%3};"
        : "+f"(c[0]), "+f"(c[1]), "+f"(c[2]), "+f"(c[3])
        : "r"(a[0]), "r"(a[1]), "r"(a[2]), "r"(a[3]), "r"(b[0]), "r"(b[1]));
}
#define SWZ(o) ((o) ^ (((o) >> 3) & 0x70))

// ---------------------------------------------------------------------------
// fp16 mma GEMM with fused epilogues.
// MODE 0: C(f32)[M,N] = A@W^T + bias0 (+resid)
// MODE 1: interleaved gate pair -> __half2(rem, z) at [M, HQ]
// MODE 2: interleaved swiglu pair -> __half ff at [M, HQ]
// MT=2 -> BM=128 @2CTA/SM. NSTG cp.async stages. BN=128, 256 thr, 4x2 warps.
// ---------------------------------------------------------------------------
template <int MODE, int MT, int NSTG>
__global__ __launch_bounds__(256, (MT == 2 ? 2 : 1))
void gemm_h(const __half* __restrict__ A, int K,
            const __half* __restrict__ W,
            const float* __restrict__ bias0,
            const float* __restrict__ bias1,
            const float* __restrict__ resid,
            void* __restrict__ outp, int N)
{
    constexpr int BMv = 64 * MT;
    constexpr int A_ST = BMv * 128;
    constexpr int B_ST = 16384;
    constexpr int ST = A_ST + B_ST;

    extern __shared__ char sm[];
    int tid = threadIdx.x;
    int wid = tid >> 5, lane = tid & 31;
    int wm = wid >> 1, wn = wid & 1;
    int m0 = blockIdx.y * BMv, n0 = blockIdx.x * 128;
    int nk = K >> 6;
    uint32_t sbase = smem_u32(sm);

    float acc[MT][8][4];
    #pragma unroll
    for (int i = 0; i < MT; i++)
        #pragma unroll
        for (int j = 0; j < 8; j++)
            #pragma unroll
            for (int r = 0; r < 4; r++) acc[i][j][r] = 0.f;

    auto load_stage = [&](int s, int kc) {
        uint32_t sa = sbase + s * ST;
        int kb = kc * 64;
        #pragma unroll
        for (int i = 0; i < 2 * MT; i++) {
            int idx = i * 256 + tid;
            int row = idx >> 3, c8 = idx & 7;
            cp_async16(sa + SWZ(row * 128 + c8 * 16),
                       A + (size_t)(m0 + row) * K + kb + c8 * 8);
        }
        #pragma unroll
        for (int i = 0; i < 4; i++) {
            int idx = i * 256 + tid;
            int row = idx >> 3, c8 = idx & 7;
            cp_async16(sa + A_ST + SWZ(row * 128 + c8 * 16),
                       W + (size_t)(n0 + row) * K + kb + c8 * 8);
        }
        cp_commit();
    };

    #pragma unroll
    for (int s = 0; s < NSTG - 1; s++) load_stage(s, s);

    for (int k0 = 0; k0 < nk; k0++) {
        cp_wait<NSTG - 2>();
        __syncthreads();
        if (k0 + NSTG - 1 < nk) load_stage((k0 + NSTG - 1) % NSTG, k0 + NSTG - 1);

        uint32_t saA = sbase + (k0 % NSTG) * ST;
        uint32_t saB = saA + A_ST;

        #pragma unroll
        for (int kk = 0; kk < 4; kk++) {
            int kc = kk * 16;
            uint32_t af[MT][4], bf[8][2];
            #pragma unroll
            for (int mt = 0; mt < MT; mt++) {
                int row = wm * (16 * MT) + mt * 16 + (lane & 15);
                int colh = kc + ((lane >> 4) << 3);
                ldsm_x4(af[mt], saA + SWZ(row * 128 + colh * 2));
            }
            #pragma unroll
            for (int np = 0; np < 4; np++) {
                uint32_t r[4];
                int n = wn * 64 + np * 16 + (lane & 7) + ((lane >> 4) << 3);
                int colh = kc + (((lane >> 3) & 1) << 3);
                ldsm_x4(r, saB + SWZ(n * 128 + colh * 2));
                bf[np * 2 + 0][0] = r[0]; bf[np * 2 + 0][1] = r[1];
                bf[np * 2 + 1][0] = r[2]; bf[np * 2 + 1][1] = r[3];
            }
            #pragma unroll
            for (int mt = 0; mt < MT; mt++)
                #pragma unroll
                for (int nt = 0; nt < 8; nt++)
                    mma_f16(acc[mt][nt], af[mt], bf[nt]);
        }
        // no trailing __syncthreads: top-of-loop cp_wait+sync suffices
    }

    int g = lane >> 2, t = lane & 3;
    #pragma unroll
    for (int mt = 0; mt < MT; mt++) {
        #pragma unroll
        for (int nt = 0; nt < 8; nt++) {
            int col = n0 + wn * 64 + nt * 8 + 2 * t;
            int row = m0 + wm * (16 * MT) + mt * 16 + g;
            if (MODE == 0) {
                float2 b2 = *reinterpret_cast<const float2*>(&bias0[col]);
                #pragma unroll
                for (int hr = 0; hr < 2; hr++) {
                    size_t off = (size_t)(row + hr * 8) * N + col;
                    float2 v;
                    v.x = acc[mt][nt][hr * 2 + 0] + b2.x;
                    v.y = acc[mt][nt][hr * 2 + 1] + b2.y;
                    if (resid) {
                        float2 q = *reinterpret_cast<const float2*>(&resid[off]);
                        v.x += q.x; v.y += q.y;
                    }
                    *reinterpret_cast<float2*>(&((float*)outp)[off]) = v;
                }
            } else {
                int h = col >> 1;
                float bf0 = bias0[h], bf1 = bias1[h];
                #pragma unroll
                for (int hr = 0; hr < 2; hr++) {
                    size_t off = (size_t)(row + hr * 8) * HQ + h;
                    float c0 = acc[mt][nt][hr * 2 + 0] + bf0;
                    float c1 = acc[mt][nt][hr * 2 + 1] + bf1;
                    if (MODE == 1) {
                        float decay = (float)h * (1.0f / (float)(HQ - 1));
                        float rem = decay / (1.0f + expf(-c0));
                        float z = tanhf(c1) * rem;
                        ((__half2*)outp)[off] = __floats2half2_rn(rem, z);
                    } else {
                        float ff = c0 * c1 / (1.0f + expf(-c1));
                        ((__half*)outp)[off] = __float2half_rn(ff);
                    }
                }
            }
        }
    }
}

// ---------------- conversions / elementwise ----------------
__global__ void wconv_all(const float* __restrict__ w_f,  const float* __restrict__ w_i,
                          const float* __restrict__ w_fc, const float* __restrict__ w_fa,
                          const float* __restrict__ w_ho, const float* __restrict__ w_fo,
                          __half* __restrict__ wh)
{
    const size_t WSL = (size_t)HQ * DQ;
    size_t i4 = ((size_t)blockIdx.x * blockDim.x + threadIdx.x) * 4;
    int seg = blockIdx.y;
    if (seg < 2) {
        const float* a = seg ? w_fc : w_f;
        const float* b = seg ? w_fa : w_i;
        __half* out = wh + (size_t)seg * 2 * WSL;
        int j = (int)(i4 >> 10);
        int k = (int)(i4 & (DQ - 1));
        float4 va = *reinterpret_cast<const float4*>(a + i4);
        float4 vb = *reinterpret_cast<const float4*>(b + i4);
        __half2* oa = reinterpret_cast<__half2*>(out + ((size_t)(2 * j) * DQ + k));
        __half2* ob = reinterpret_cast<__half2*>(out + ((size_t)(2 * j + 1) * DQ + k));
        oa[0] = __floats2half2_rn(va.x, va.y);
        oa[1] = __floats2half2_rn(va.z, va.w);
        ob[0] = __floats2half2_rn(vb.x, vb.y);
        ob[1] = __floats2half2_rn(vb.z, vb.w);
    } else {
        const float* w = (seg == 2) ? w_ho : w_fo;
        __half* out = wh + (size_t)(seg + 2) * WSL;
        float4 v = *reinterpret_cast<const float4*>(w + i4);
        __half2* o = reinterpret_cast<__half2*>(out + i4);
        o[0] = __floats2half2_rn(v.x, v.y);
        o[1] = __floats2half2_rn(v.z, v.w);
    }
}

__global__ void rmsnorm_h(const float* __restrict__ x,
                          const float* __restrict__ g,
                          __half* __restrict__ out)
{
    int row = blockIdx.x, tid = threadIdx.x;
    float4 v = reinterpret_cast<const float4*>(x + (size_t)row * DQ)[tid];
    float s = v.x * v.x + v.y * v.y + v.z * v.z + v.w * v.w;
    #pragma unroll
    for (int o = 16; o > 0; o >>= 1) s += __shfl_xor_sync(0xFFFFFFFFu, s, o);
    __shared__ float red[8];
    __shared__ float scale_s;
    if ((tid & 31) == 0) red[tid >> 5] = s;
    __syncthreads();
    if (tid == 0) {
        float tt = 0.f;
        #pragma unroll
        for (int i = 0; i < 8; i++) tt += red[i];
        scale_s = rsqrtf(tt * (1.0f / DQ) + 1e-6f);
    }
    __syncthreads();
    float sc = scale_s;
    float4 gg = reinterpret_cast<const float4*>(g)[tid];
    __half2* o2 = reinterpret_cast<__half2*>(out + (size_t)row * DQ) + tid * 2;
    o2[0] = __floats2half2_rn(v.x * sc * gg.x, v.y * sc * gg.y);
    o2[1] = __floats2half2_rn(v.z * sc * gg.z, v.w * sc * gg.w);
}

// chunked scan over __half2(rem, z): NCH chunks x CLEN steps (grid 1024 blocks)
__global__ void scan_p1(const __half2* __restrict__ rz,
                        float* __restrict__ sA, float* __restrict__ sB)
{
    int tg = blockIdx.x * blockDim.x + threadIdx.x;    // 0 .. NCH*8192-1
    int chunk = tg >> 13, c = tg & 8191;
    int b = c >> 11, hh = c & (HQ - 1);
    size_t base = ((size_t)b * LQ + chunk * CLEN) * HQ + hh;
    float Aa = 1.f, Bb = 0.f;
    #pragma unroll 4
    for (int t = 0; t < CLEN; t++) {
        float2 v = __half22float2(rz[base + (size_t)t * HQ]);
        float f = 1.0f - v.x;
        Bb = fmaf(f, Bb, v.y);
        Aa *= f;
    }
    sA[tg] = Aa; sB[tg] = Bb;
}

__global__ void scan_p2(const float* __restrict__ h0,
                        const float* __restrict__ sA, const float* __restrict__ sB,
                        float* __restrict__ sS, float* __restrict__ hlast)
{
    int c = blockIdx.x * blockDim.x + threadIdx.x;
    float h = h0[c];
    #pragma unroll
    for (int k = 0; k < NCH; k++) {
        sS[k * 8192 + c] = h;
        h = fmaf(sA[k * 8192 + c], h, sB[k * 8192 + c]);
    }
    hlast[c] = h;
}

__global__ void scan_p3(const __half2* __restrict__ rz,
                        const float* __restrict__ sS, __half* __restrict__ out)
{
    int tg = blockIdx.x * blockDim.x + threadIdx.x;
    int chunk = tg >> 13, c = tg & 8191;
    int b = c >> 11, hh = c & (HQ - 1);
    size_t base = ((size_t)b * LQ + chunk * CLEN) * HQ + hh;
    float h = sS[tg];
    #pragma unroll 4
    for (int t = 0; t < CLEN; t++) {
        size_t i = base + (size_t)t * HQ;
        float2 v = __half22float2(rz[i]);
        h = fmaf(1.0f - v.x, h, v.y);
        out[i] = __float2half_rn(h);
    }
}

// ---------------- launch ----------------
extern "C" void kernel_launch(void* const* d_in, const int* in_sizes, int n_in,
                              void* d_out, int out_size)
{
    const float* x      = (const float*)d_in[0];
    const float* hidden = (const float*)d_in[1];
    const float* w_f    = (const float*)d_in[2];
    const float* b_f    = (const float*)d_in[3];
    const float* w_i    = (const float*)d_in[4];
    const float* b_i    = (const float*)d_in[5];
    const float* w_ho   = (const float*)d_in[6];
    const float* b_ho   = (const float*)d_in[7];
    const float* w_fc   = (const float*)d_in[8];
    const float* b_fc   = (const float*)d_in[9];
    const float* w_fa   = (const float*)d_in[10];
    const float* b_fa   = (const float*)d_in[11];
    const float* w_fo   = (const float*)d_in[12];
    const float* b_fo   = (const float*)d_in[13];
    const float* g1     = (const float*)d_in[14];
    const float* g2     = (const float*)d_in[15];

    float* out_main  = (float*)d_out;
    float* out_hlast = out_main + (size_t)BLQ * DQ;

    __half *xnh, *hh, *wh;
    __half2* rz;
    float *x1, *sA, *sB, *sS;
    cudaGetSymbolAddress((void**)&xnh, g_xnh);
    cudaGetSymbolAddress((void**)&hh,  g_hh);
    cudaGetSymbolAddress((void**)&wh,  g_wh);
    cudaGetSymbolAddress((void**)&rz,  g_rz);
    cudaGetSymbolAddress((void**)&x1,  g_x1);
    cudaGetSymbolAddress((void**)&sA,  g_sA);
    cudaGetSymbolAddress((void**)&sB,  g_sB);
    cudaGetSymbolAddress((void**)&sS,  g_sS);

    const size_t WSL = (size_t)HQ * DQ;   // 2M halves
    __half* wpfi   = wh + 0 * WSL;        // interleaved [4096,1024]
    __half* wpfcfa = wh + 2 * WSL;        // interleaved [4096,1024]
    __half* whho   = wh + 4 * WSL;        // [1024,2048]
    __half* whfo   = wh + 5 * WSL;        // [1024,2048]

    // All GEMMs MT=2, NST=3 -> 98304 B smem, 2 CTAs/SM
    const int SMEM_G = 3 * (16384 + 16384);
    cudaFuncSetAttribute(gemm_h<0,2,3>, cudaFuncAttributeMaxDynamicSharedMemorySize, SMEM_G);
    cudaFuncSetAttribute(gemm_h<1,2,3>, cudaFuncAttributeMaxDynamicSharedMemorySize, SMEM_G);
    cudaFuncSetAttribute(gemm_h<2,2,3>, cudaFuncAttributeMaxDynamicSharedMemorySize, SMEM_G);

    wconv_all<<<dim3(2048, 4), 256>>>(w_f, w_i, w_fc, w_fa, w_ho, w_fo, wh);

    dim3 gPair(2 * HQ / 128, BLQ / 128);   // (32, 128)
    dim3 gHD(DQ / 128, BLQ / 128);         // (8, 128)

    rmsnorm_h<<<BLQ, 256>>>(x, g1, xnh);
    gemm_h<1,2,3><<<gPair, 256, SMEM_G>>>(xnh, DQ, wpfi, b_f, b_i, nullptr, rz, HQ);
    scan_p1<<<NCH * 32, 256>>>(rz, sA, sB);
    scan_p2<<<32, 256>>>(hidden, sA, sB, sS, out_hlast);
    scan_p3<<<NCH * 32, 256>>>(rz, sS, hh);
    gemm_h<0,2,3><<<gHD, 256, SMEM_G>>>(hh, HQ, whho, b_ho, nullptr, x, x1, DQ);
    rmsnorm_h<<<BLQ, 256>>>(x1, g2, xnh);
    gemm_h<2,2,3><<<gPair, 256, SMEM_G>>>(xnh, DQ, wpfcfa, b_fc, b_fa, nullptr, hh, HQ);
    gemm_h<0,2,3><<<gHD, 256, SMEM_G>>>(hh, HQ, whfo, b_fo, nullptr, x1, out_main, DQ);
}

// round 17
// speedup vs baseline: 1.5091x; 1.5091x over previous
#include <cuda_runtime.h>
#include <cuda_fp16.h>
#include <math.h>
#include <stdint.h>

#define BQ 4
#define LQ 4096
#define DQ 1024
#define HQ 2048
#define BLQ 16384
#define NCH 32            // scan chunks
#define CLEN 128          // steps per chunk (NCH*CLEN = LQ)

// Scratch
__device__ __half  g_xnh[(size_t)BLQ * DQ];
__device__ __half  g_hh [(size_t)BLQ * HQ];          // h, then ff
__device__ __half  g_wh [6 * (size_t)HQ * DQ];       // wpfi(2), wpfcfa(2), whho(1), whfo(1)
__device__ __half2 g_rz [(size_t)BLQ * HQ];
__device__ float g_x1[(size_t)BLQ * DQ];
__device__ float g_sA[NCH * 8192];
__device__ float g_sB[NCH * 8192];
__device__ float g_sS[NCH * 8192];

__device__ __forceinline__ void cp_async16(uint32_t saddr, const void* gptr) {
    asm volatile("cp.async.cg.shared.global [%0], [%1], 16;" :: "r"(saddr), "l"(gptr));
}
__device__ __forceinline__ void cp_commit() {
    asm volatile("cp.async.commit_group;" ::: "memory");
}
template <int N>
__device__ __forceinline__ void cp_wait() {
    asm volatile("cp.async.wait_group %0;" :: "n"(N) : "memory");
}
__device__ __forceinline__ uint32_t smem_u32(const void* p) {
    uint32_t a;
    asm("{ .reg .u64 t; cvta.to.shared.u64 t, %1; cvt.u32.u64 %0, t; }"
        : "=r"(a) : "l"(p));
    return a;
}
__device__ __forceinline__ void ldsm_x4(uint32_t* r, uint32_t addr) {
    asm volatile("ldmatrix.sync.aligned.m8n8.x4.shared.b16 {%0,%1,%2,%3}, [%4];"
        : "=r"(r[0]), "=r"(r[1]), "=r"(r[2]), "=r"(r[3]) : "r"(addr));
}
__device__ __forceinline__ void mma_f16(float* c, const uint32_t* a, const uint32_t* b) {
    asm volatile(
        "mma.sync.aligned.m16n8k16.row.col.f32.f16.f16.f32 "
        "{%0,%1,%2,%3}, {%4,%5,%6,%7}, {%8,%9}, {%0,%1,%2,%3};"
        : "+f"(c[0]), "+f"(c[1]), "+f"(c[2]), "+f"(c[3])
        : "r"(a[0]), "r"(a[1]), "r"(a[2]), "r"(a[3]), "r"(b[0]), "r"(b[1]));
}
#define SWZ(o) ((o) ^ (((o) >> 3) & 0x70))

// ---------------------------------------------------------------------------
// fp16 mma GEMM with fused epilogues.
// MODE 0: C(f32)[M,N] = A@W^T + bias0 (+resid)
// MODE 1: interleaved gate pair -> __half2(rem, z) at [M, HQ]
// MODE 2: interleaved swiglu pair -> __half ff at [M, HQ]
// MT=2 -> BM=128 @2CTA/SM. NSTG cp.async stages. BN=128, 256 thr, 4x2 warps.
// ---------------------------------------------------------------------------
template <int MODE, int MT, int NSTG>
__global__ __launch_bounds__(256, (MT == 2 ? 2 : 1))
void gemm_h(const __half* __restrict__ A, int K,
            const __half* __restrict__ W,
            const float* __restrict__ bias0,
            const float* __restrict__ bias1,
            const float* __restrict__ resid,
            void* __restrict__ outp, int N)
{
    constexpr int BMv = 64 * MT;
    constexpr int A_ST = BMv * 128;
    constexpr int B_ST = 16384;
    constexpr int ST = A_ST + B_ST;

    extern __shared__ char sm[];
    int tid = threadIdx.x;
    int wid = tid >> 5, lane = tid & 31;
    int wm = wid >> 1, wn = wid & 1;
    int m0 = blockIdx.y * BMv, n0 = blockIdx.x * 128;
    int nk = K >> 6;
    uint32_t sbase = smem_u32(sm);

    float acc[MT][8][4];
    #pragma unroll
    for (int i = 0; i < MT; i++)
        #pragma unroll
        for (int j = 0; j < 8; j++)
            #pragma unroll
            for (int r = 0; r < 4; r++) acc[i][j][r] = 0.f;

    auto load_stage = [&](int s, int kc) {
        uint32_t sa = sbase + s * ST;
        int kb = kc * 64;
        #pragma unroll
        for (int i = 0; i < 2 * MT; i++) {
            int idx = i * 256 + tid;
            int row = idx >> 3, c8 = idx & 7;
            cp_async16(sa + SWZ(row * 128 + c8 * 16),
                       A + (size_t)(m0 + row) * K + kb + c8 * 8);
        }
        #pragma unroll
        for (int i = 0; i < 4; i++) {
            int idx = i * 256 + tid;
            int row = idx >> 3, c8 = idx & 7;
            cp_async16(sa + A_ST + SWZ(row * 128 + c8 * 16),
                       W + (size_t)(n0 + row) * K + kb + c8 * 8);
        }
        cp_commit();
    };

    #pragma unroll
    for (int s = 0; s < NSTG - 1; s++) load_stage(s, s);

    for (int k0 = 0; k0 < nk; k0++) {
        cp_wait<NSTG - 2>();
        __syncthreads();
        if (k0 + NSTG - 1 < nk) load_stage((k0 + NSTG - 1) % NSTG, k0 + NSTG - 1);

        uint32_t saA = sbase + (k0 % NSTG) * ST;
        uint32_t saB = saA + A_ST;

        #pragma unroll
        for (int kk = 0; kk < 4; kk++) {
            int kc = kk * 16;
            uint32_t af[MT][4], bf[8][2];
            #pragma unroll
            for (int mt = 0; mt < MT; mt++) {
                int row = wm * (16 * MT) + mt * 16 + (lane & 15);
                int colh = kc + ((lane >> 4) << 3);
                ldsm_x4(af[mt], saA + SWZ(row * 128 + colh * 2));
            }
            #pragma unroll
            for (int np = 0; np < 4; np++) {
                uint32_t r[4];
                int n = wn * 64 + np * 16 + (lane & 7) + ((lane >> 4) << 3);
                int colh = kc + (((lane >> 3) & 1) << 3);
                ldsm_x4(r, saB + SWZ(n * 128 + colh * 2));
                bf[np * 2 + 0][0] = r[0]; bf[np * 2 + 0][1] = r[1];
                bf[np * 2 + 1][0] = r[2]; bf[np * 2 + 1][1] = r[3];
            }
            #pragma unroll
            for (int mt = 0; mt < MT; mt++)
                #pragma unroll
                for (int nt = 0; nt < 8; nt++)
                    mma_f16(acc[mt][nt], af[mt], bf[nt]);
        }
        // no trailing __syncthreads: top-of-loop cp_wait+sync suffices
    }

    int g = lane >> 2, t = lane & 3;
    #pragma unroll
    for (int mt = 0; mt < MT; mt++) {
        #pragma unroll
        for (int nt = 0; nt < 8; nt++) {
            int col = n0 + wn * 64 + nt * 8 + 2 * t;
            int row = m0 + wm * (16 * MT) + mt * 16 + g;
            if (MODE == 0) {
                float2 b2 = *reinterpret_cast<const float2*>(&bias0[col]);
                #pragma unroll
                for (int hr = 0; hr < 2; hr++) {
                    size_t off = (size_t)(row + hr * 8) * N + col;
                    float2 v;
                    v.x = acc[mt][nt][hr * 2 + 0] + b2.x;
                    v.y = acc[mt][nt][hr * 2 + 1] + b2.y;
                    if (resid) {
                        float2 q = *reinterpret_cast<const float2*>(&resid[off]);
                        v.x += q.x; v.y += q.y;
                    }
                    *reinterpret_cast<float2*>(&((float*)outp)[off]) = v;
                }
            } else {
                int h = col >> 1;
                float bf0 = bias0[h], bf1 = bias1[h];
                #pragma unroll
                for (int hr = 0; hr < 2; hr++) {
                    size_t off = (size_t)(row + hr * 8) * HQ + h;
                    float c0 = acc[mt][nt][hr * 2 + 0] + bf0;
                    float c1 = acc[mt][nt][hr * 2 + 1] + bf1;
                    if (MODE == 1) {
                        float decay = (float)h * (1.0f / (float)(HQ - 1));
                        float rem = decay / (1.0f + expf(-c0));
                        float z = tanhf(c1) * rem;
                        ((__half2*)outp)[off] = __floats2half2_rn(rem, z);
                    } else {
                        float ff = c0 * c1 / (1.0f + expf(-c1));
                        ((__half*)outp)[off] = __float2half_rn(ff);
                    }
                }
            }
        }
    }
}

// ---------------- conversions / elementwise ----------------
__global__ void wconv_all(const float* __restrict__ w_f,  const float* __restrict__ w_i,
                          const float* __restrict__ w_fc, const float* __restrict__ w_fa,
                          const float* __restrict__ w_ho, const float* __restrict__ w_fo,
                          __half* __restrict__ wh)
{
    const size_t WSL = (size_t)HQ * DQ;
    size_t i4 = ((size_t)blockIdx.x * blockDim.x + threadIdx.x) * 4;
    int seg = blockIdx.y;
    if (seg < 2) {
        const float* a = seg ? w_fc : w_f;
        const float* b = seg ? w_fa : w_i;
        __half* out = wh + (size_t)seg * 2 * WSL;
        int j = (int)(i4 >> 10);
        int k = (int)(i4 & (DQ - 1));
        float4 va = *reinterpret_cast<const float4*>(a + i4);
        float4 vb = *reinterpret_cast<const float4*>(b + i4);
        __half2* oa = reinterpret_cast<__half2*>(out + ((size_t)(2 * j) * DQ + k));
        __half2* ob = reinterpret_cast<__half2*>(out + ((size_t)(2 * j + 1) * DQ + k));
        oa[0] = __floats2half2_rn(va.x, va.y);
        oa[1] = __floats2half2_rn(va.z, va.w);
        ob[0] = __floats2half2_rn(vb.x, vb.y);
        ob[1] = __floats2half2_rn(vb.z, vb.w);
    } else {
        const float* w = (seg == 2) ? w_ho : w_fo;
        __half* out = wh + (size_t)(seg + 2) * WSL;
        float4 v = *reinterpret_cast<const float4*>(w + i4);
        __half2* o = reinterpret_cast<__half2*>(out + i4);
        o[0] = __floats2half2_rn(v.x, v.y);
        o[1] = __floats2half2_rn(v.z, v.w);
    }
}

__global__ void rmsnorm_h(const float* __restrict__ x,
                          const float* __restrict__ g,
                          __half* __restrict__ out)
{
    int row = blockIdx.x, tid = threadIdx.x;
    float4 v = reinterpret_cast<const float4*>(x + (size_t)row * DQ)[tid];
    float s = v.x * v.x + v.y * v.y + v.z * v.z + v.w * v.w;
    #pragma unroll
    for (int o = 16; o > 0; o >>= 1) s += __shfl_xor_sync(0xFFFFFFFFu, s, o);
    __shared__ float red[8];
    __shared__ float scale_s;
    if ((tid & 31) == 0) red[tid >> 5] = s;
    __syncthreads();
    if (tid == 0) {
        float tt = 0.f;
        #pragma unroll
        for (int i = 0; i < 8; i++) tt += red[i];
        scale_s = rsqrtf(tt * (1.0f / DQ) + 1e-6f);
    }
    __syncthreads();
    float sc = scale_s;
    float4 gg = reinterpret_cast<const float4*>(g)[tid];
    __half2* o2 = reinterpret_cast<__half2*>(out + (size_t)row * DQ) + tid * 2;
    o2[0] = __floats2half2_rn(v.x * sc * gg.x, v.y * sc * gg.y);
    o2[1] = __floats2half2_rn(v.z * sc * gg.z, v.w * sc * gg.w);
}

// chunked scan over __half2(rem, z): NCH chunks x CLEN steps (grid 1024 blocks)
__global__ void scan_p1(const __half2* __restrict__ rz,
                        float* __restrict__ sA, float* __restrict__ sB)
{
    int tg = blockIdx.x * blockDim.x + threadIdx.x;    // 0 .. NCH*8192-1
    int chunk = tg >> 13, c = tg & 8191;
    int b = c >> 11, hh = c & (HQ - 1);
    size_t base = ((size_t)b * LQ + chunk * CLEN) * HQ + hh;
    float Aa = 1.f, Bb = 0.f;
    #pragma unroll 4
    for (int t = 0; t < CLEN; t++) {
        float2 v = __half22float2(rz[base + (size_t)t * HQ]);
        float f = 1.0f - v.x;
        Bb = fmaf(f, Bb, v.y);
        Aa *= f;
    }
    sA[tg] = Aa; sB[tg] = Bb;
}

__global__ void scan_p2(const float* __restrict__ h0,
                        const float* __restrict__ sA, const float* __restrict__ sB,
                        float* __restrict__ sS, float* __restrict__ hlast)
{
    int c = blockIdx.x * blockDim.x + threadIdx.x;
    float h = h0[c];
    #pragma unroll
    for (int k = 0; k < NCH; k++) {
        sS[k * 8192 + c] = h;
        h = fmaf(sA[k * 8192 + c], h, sB[k * 8192 + c]);
    }
    hlast[c] = h;
}

__global__ void scan_p3(const __half2* __restrict__ rz,
                        const float* __restrict__ sS, __half* __restrict__ out)
{
    int tg = blockIdx.x * blockDim.x + threadIdx.x;
    int chunk = tg >> 13, c = tg & 8191;
    int b = c >> 11, hh = c & (HQ - 1);
    size_t base = ((size_t)b * LQ + chunk * CLEN) * HQ + hh;
    float h = sS[tg];
    #pragma unroll 4
    for (int t = 0; t < CLEN; t++) {
        size_t i = base + (size_t)t * HQ;
        float2 v = __half22float2(rz[i]);
        h = fmaf(1.0f - v.x, h, v.y);
        out[i] = __float2half_rn(h);
    }
}

// ---------------- launch ----------------
extern "C" void kernel_launch(void* const* d_in, const int* in_sizes, int n_in,
                              void* d_out, int out_size)
{
    const float* x      = (const float*)d_in[0];
    const float* hidden = (const float*)d_in[1];
    const float* w_f    = (const float*)d_in[2];
    const float* b_f    = (const float*)d_in[3];
    const float* w_i    = (const float*)d_in[4];
    const float* b_i    = (const float*)d_in[5];
    const float* w_ho   = (const float*)d_in[6];
    const float* b_ho   = (const float*)d_in[7];
    const float* w_fc   = (const float*)d_in[8];
    const float* b_fc   = (const float*)d_in[9];
    const float* w_fa   = (const float*)d_in[10];
    const float* b_fa   = (const float*)d_in[11];
    const float* w_fo   = (const float*)d_in[12];
    const float* b_fo   = (const float*)d_in[13];
    const float* g1     = (const float*)d_in[14];
    const float* g2     = (const float*)d_in[15];

    float* out_main  = (float*)d_out;
    float* out_hlast = out_main + (size_t)BLQ * DQ;

    __half *xnh, *hh, *wh;
    __half2* rz;
    float *x1, *sA, *sB, *sS;
    cudaGetSymbolAddress((void**)&xnh, g_xnh);
    cudaGetSymbolAddress((void**)&hh,  g_hh);
    cudaGetSymbolAddress((void**)&wh,  g_wh);
    cudaGetSymbolAddress((void**)&rz,  g_rz);
    cudaGetSymbolAddress((void**)&x1,  g_x1);
    cudaGetSymbolAddress((void**)&sA,  g_sA);
    cudaGetSymbolAddress((void**)&sB,  g_sB);
    cudaGetSymbolAddress((void**)&sS,  g_sS);

    const size_t WSL = (size_t)HQ * DQ;   // 2M halves
    __half* wpfi   = wh + 0 * WSL;        // interleaved [4096,1024]
    __half* wpfcfa = wh + 2 * WSL;        // interleaved [4096,1024]
    __half* whho   = wh + 4 * WSL;        // [1024,2048]
    __half* whfo   = wh + 5 * WSL;        // [1024,2048]

    // All GEMMs MT=2, NST=3 -> 98304 B smem, 2 CTAs/SM
    const int SMEM_G = 3 * (16384 + 16384);
    cudaFuncSetAttribute(gemm_h<0,2,3>, cudaFuncAttributeMaxDynamicSharedMemorySize, SMEM_G);
    cudaFuncSetAttribute(gemm_h<1,2,3>, cudaFuncAttributeMaxDynamicSharedMemorySize, SMEM_G);
    cudaFuncSetAttribute(gemm_h<2,2,3>, cudaFuncAttributeMaxDynamicSharedMemorySize, SMEM_G);

    wconv_all<<<dim3(2048, 4), 256>>>(w_f, w_i, w_fc, w_fa, w_ho, w_fo, wh);

    dim3 gPair(2 * HQ / 128, BLQ / 128);   // (32, 128)
    dim3 gHD(DQ / 128, BLQ / 128);         // (8, 128)

    rmsnorm_h<<<BLQ, 256>>>(x, g1, xnh);
    gemm_h<1,2,3><<<gPair, 256, SMEM_G>>>(xnh, DQ, wpfi, b_f, b_i, nullptr, rz, HQ);
    scan_p1<<<NCH * 32, 256>>>(rz, sA, sB);
    scan_p2<<<32, 256>>>(hidden, sA, sB, sS, out_hlast);
    scan_p3<<<NCH * 32, 256>>>(rz, sS, hh);
    gemm_h<0,2,3><<<gHD, 256, SMEM_G>>>(hh, HQ, whho, b_ho, nullptr, x, x1, DQ);
    rmsnorm_h<<<BLQ, 256>>>(x1, g2, xnh);
    gemm_h<2,2,3><<<gPair, 256, SMEM_G>>>(xnh, DQ, wpfcfa, b_fc, b_fa, nullptr, hh, HQ);
    gemm_h<0,2,3><<<gHD, 256, SMEM_G>>>(hh, HQ, whfo, b_fo, nullptr, x1, out_main, DQ);
}